// round 15
// baseline (speedup 1.0000x reference)
#include <cuda_runtime.h>
#include <cstdint>

#define NTHREADS 256
#define NBLOCKS  (148 * 2)
#define HSTRIDE  20   // h row stride in uint2 units -> conflict-free A loads

// ---------------- SMEM byte offsets ----------------
#define OB_B1F   0        // W1 frags uint4: 32 frags * 32 lanes * 16B = 16384
#define OB_B2F   16384    // W2 frags uint4: 64 * 32 * 16 = 32768
#define OB_B3F   49152    // W3 frags uint4: 16 * 32 * 16 = 8192
#define OB_H     57344    // h uint2 (hi,lo): 256 rows * 20 w * 8B = 40960
#define OB_b1    98304    // 128 f
#define OB_b2    98816    // 64 f
#define OB_b3    99072    // 32 f
#define OB_w4    99200    // 32 f
#define OB_b4    99328
#define OB_wih   99332    // 32 f
#define OB_whh   99460    // 16 f
#define OB_bias  99524    // 8 f
#define SMEM_BYTES 99584

// ---------------- helpers ----------------
// split (a,b) -> hi word (truncated bf16 pair, a low) + lo word (RN residuals)
__device__ __forceinline__ void splitpack(float a, float b, uint32_t& hi, uint32_t& lo) {
    uint32_t ua = __float_as_uint(a), ub = __float_as_uint(b);
    asm("prmt.b32 %0, %1, %2, 0x7632;" : "=r"(hi) : "r"(ua), "r"(ub));
    float ra = a - __uint_as_float(ua & 0xFFFF0000u);
    float rb = b - __uint_as_float(ub & 0xFFFF0000u);
    asm("cvt.rn.bf16x2.f32 %0, %1, %2;" : "=r"(lo) : "f"(rb), "f"(ra));
}
__device__ __forceinline__ void mma_bf16(float* c, const uint32_t* a, uint32_t b0, uint32_t b1) {
    asm volatile(
        "mma.sync.aligned.m16n8k16.row.col.f32.bf16.bf16.f32 "
        "{%0,%1,%2,%3}, {%4,%5,%6,%7}, {%8,%9}, {%0,%1,%2,%3};"
        : "+f"(c[0]), "+f"(c[1]), "+f"(c[2]), "+f"(c[3])
        : "r"(a[0]), "r"(a[1]), "r"(a[2]), "r"(a[3]), "r"(b0), "r"(b1));
}
__device__ __forceinline__ float sigf(float x) {
    float e = __expf(-x);
    return __fdividef(1.0f, 1.0f + e);
}
__device__ __forceinline__ float tanhfast(float x) {
    float e = __expf(-2.0f * x);
    return __fdividef(2.0f, 1.0f + e) - 1.0f;
}

__global__ void __launch_bounds__(NTHREADS, 2)
lstm_mlp_mma_kernel(const float* __restrict__ x,
                    const float* __restrict__ W_ih, const float* __restrict__ W_hh,
                    const float* __restrict__ b_ih, const float* __restrict__ b_hh,
                    const float* __restrict__ W1, const float* __restrict__ b1,
                    const float* __restrict__ W2, const float* __restrict__ b2,
                    const float* __restrict__ W3, const float* __restrict__ b3,
                    const float* __restrict__ W4, const float* __restrict__ b4,
                    float* __restrict__ out, int n)
{
    extern __shared__ char smem[];
    const int tid  = threadIdx.x;
    const int lane = tid & 31;

    uint4* sB1f = (uint4*)(smem + OB_B1F);
    uint4* sB2f = (uint4*)(smem + OB_B2F);
    uint4* sB3f = (uint4*)(smem + OB_B3F);
    uint2* sH   = (uint2*)(smem + OB_H);
    float* sb1  = (float*)(smem + OB_b1);
    float* sb2  = (float*)(smem + OB_b2);
    float* sb3  = (float*)(smem + OB_b3);
    float* sw4  = (float*)(smem + OB_w4);
    float* sb4  = (float*)(smem + OB_b4);
    float* sWih = (float*)(smem + OB_wih);
    float* sWhh = (float*)(smem + OB_whh);
    float* sBias= (float*)(smem + OB_bias);

    // ---- stage small params ----
    if (tid < 128) sb1[tid] = b1[tid];
    if (tid < 64)  sb2[tid] = b2[tid];
    if (tid < 32)  { sb3[tid] = b3[tid]; sw4[tid] = W4[tid]; }
    if (tid == 0)  sb4[0] = b4[0];
    if (tid < 32)  sWih[tid] = W_ih[tid];
    if (tid < 16)  sWhh[tid] = W_hh[tid];
    if (tid < 8)   sBias[tid] = b_ih[tid] + b_hh[tid];

    // ---- precompute B fragments, hi/lo interleaved as uint4 ----
    // W1 [128,20], K padded to 32: 2 kc x 16 nt
    for (int e = tid; e < 32 * 32; e += NTHREADS) {
        int l = e & 31, f = e >> 5;
        int kc = f >> 4, nt = f & 15;
        int col = nt * 8 + (l >> 2);
        int k0 = kc * 16 + (l & 3) * 2;
        float v00 = (k0     < 20) ? W1[col * 20 + k0]     : 0.f;
        float v01 = (k0 + 1 < 20) ? W1[col * 20 + k0 + 1] : 0.f;
        float v10 = (k0 + 8 < 20) ? W1[col * 20 + k0 + 8] : 0.f;
        float v11 = (k0 + 9 < 20) ? W1[col * 20 + k0 + 9] : 0.f;
        uint32_t h0, l0, h1, l1;
        splitpack(v00, v01, h0, l0);
        splitpack(v10, v11, h1, l1);
        sB1f[f * 32 + l] = make_uint4(h0, h1, l0, l1);
    }
    // W2 [64,128]: 8 kc x 8 nt
    for (int e = tid; e < 64 * 32; e += NTHREADS) {
        int l = e & 31, f = e >> 5;
        int kc = f >> 3, nt = f & 7;
        int col = nt * 8 + (l >> 2);
        int k0 = kc * 16 + (l & 3) * 2;
        uint32_t h0, l0, h1, l1;
        splitpack(W2[col * 128 + k0],     W2[col * 128 + k0 + 1], h0, l0);
        splitpack(W2[col * 128 + k0 + 8], W2[col * 128 + k0 + 9], h1, l1);
        sB2f[f * 32 + l] = make_uint4(h0, h1, l0, l1);
    }
    // W3 [32,64]: 4 kc x 4 nt
    for (int e = tid; e < 16 * 32; e += NTHREADS) {
        int l = e & 31, f = e >> 5;
        int kc = f >> 2, nt = f & 3;
        int col = nt * 8 + (l >> 2);
        int k0 = kc * 16 + (l & 3) * 2;
        uint32_t h0, l0, h1, l1;
        splitpack(W3[col * 64 + k0],     W3[col * 64 + k0 + 1], h0, l0);
        splitpack(W3[col * 64 + k0 + 8], W3[col * 64 + k0 + 9], h1, l1);
        sB3f[f * 32 + l] = make_uint4(h0, h1, l0, l1);
    }
    // zero K-pad words (10..15) of h array, constant across tiles
#pragma unroll
    for (int w = 10; w < 16; w++) sH[tid * HSTRIDE + w] = make_uint2(0u, 0u);
    __syncthreads();

    const float b4s = sb4[0];

    const int ntiles = (n + NTHREADS - 1) / NTHREADS;
    for (int tile = blockIdx.x; tile < ntiles; tile += gridDim.x) {
        const int row = tile * NTHREADS + tid;
        const bool valid = (row < n);

        // ================= LSTM (1 element/thread) =================
        // LSTM weights loaded from SMEM per tile (per-tile lifetime).
        {
            float rwih[32], rwhh[16], rbias[8];
#pragma unroll
            for (int i = 0; i < 32; i++) rwih[i] = sWih[i];
#pragma unroll
            for (int i = 0; i < 16; i++) rwhh[i] = sWhh[i];
#pragma unroll
            for (int i = 0; i < 8; i++)  rbias[i] = sBias[i];

            float h0 = 0.f, h1 = 0.f, c0 = 0.f, c1 = 0.f;
            const float* xp = x + (size_t)(valid ? row : 0) * 40;
#pragma unroll
            for (int t = 0; t < 10; t++) {
                float4 xt = *reinterpret_cast<const float4*>(xp + t * 4);
                float g[8];
#pragma unroll
                for (int gi = 0; gi < 8; gi++) {
                    float a = rbias[gi];
                    a = fmaf(xt.x, rwih[gi * 4 + 0], a);
                    a = fmaf(xt.y, rwih[gi * 4 + 1], a);
                    a = fmaf(xt.z, rwih[gi * 4 + 2], a);
                    a = fmaf(xt.w, rwih[gi * 4 + 3], a);
                    a = fmaf(h0, rwhh[gi * 2 + 0], a);
                    a = fmaf(h1, rwhh[gi * 2 + 1], a);
                    g[gi] = a;
                }
                float i0 = sigf(g[0]), i1 = sigf(g[1]);
                float f0 = sigf(g[2]), f1 = sigf(g[3]);
                float g0 = tanhfast(g[4]), g1 = tanhfast(g[5]);
                float o0 = sigf(g[6]), o1 = sigf(g[7]);
                c0 = fmaf(f0, c0, i0 * g0);
                c1 = fmaf(f1, c1, i1 * g1);
                h0 = o0 * tanhfast(c0);
                h1 = o1 * tanhfast(c1);
                uint32_t wh, wl;
                splitpack(h0, h1, wh, wl);
                sH[tid * HSTRIDE + t] = make_uint2(wh, wl);
            }
        }
        __syncwarp();

        // ================= MLP on tensor cores, per warp, 2 sub-tiles =================
#pragma unroll 1
        for (int s = 0; s < 2; s++) {
            const int rbase = (tid >> 5) * 32 + s * 16;
            const int r0 = rbase + (lane >> 2);

            // ---- A1 fragments for both kc (conflict-free stride-20 uint2 loads) ----
            uint32_t ah[2][4], al[2][4];
#pragma unroll
            for (int kc = 0; kc < 2; kc++) {
                const int wofs = kc * 8 + (lane & 3);
                uint2 v0 = sH[r0 * HSTRIDE + wofs];
                uint2 v1 = sH[(r0 + 8) * HSTRIDE + wofs];
                uint2 v2 = sH[r0 * HSTRIDE + wofs + 4];
                uint2 v3 = sH[(r0 + 8) * HSTRIDE + wofs + 4];
                ah[kc][0] = v0.x; al[kc][0] = v0.y;
                ah[kc][1] = v1.x; al[kc][1] = v1.y;
                ah[kc][2] = v2.x; al[kc][2] = v2.y;
                ah[kc][3] = v3.x; al[kc][3] = v3.y;
            }

            // ---- GEMM1 (groups of 4 n-tiles) + fused epilogue1 ----
            uint32_t a2h[8][4], a2l[8][4];
#pragma unroll
            for (int g = 0; g < 4; g++) {
                float c[4][4];
#pragma unroll
                for (int q = 0; q < 4; q++)
#pragma unroll
                    for (int e = 0; e < 4; e++) c[q][e] = 0.f;
#pragma unroll
                for (int kc = 0; kc < 2; kc++) {
                    uint4 f[4];
#pragma unroll
                    for (int q = 0; q < 4; q++)
                        f[q] = sB1f[(kc * 16 + 4 * g + q) * 32 + lane];
#pragma unroll
                    for (int q = 0; q < 4; q++) mma_bf16(c[q], ah[kc], f[q].x, f[q].y);
#pragma unroll
                    for (int q = 0; q < 4; q++) mma_bf16(c[q], al[kc], f[q].x, f[q].y);
#pragma unroll
                    for (int q = 0; q < 4; q++) mma_bf16(c[q], ah[kc], f[q].z, f[q].w);
                }
                // epilogue1 for these 4 n-tiles
#pragma unroll
                for (int q = 0; q < 4; q++) {
                    const int ntq = 4 * g + q;
                    const int j = ntq >> 1, hf = ntq & 1;
                    int col = ntq * 8 + (lane & 3) * 2;
                    float2 bb = *(const float2*)(sb1 + col);
                    float f0 = fmaxf(c[q][0] + bb.x, 0.f);
                    float f1 = fmaxf(c[q][1] + bb.y, 0.f);
                    float f2 = fmaxf(c[q][2] + bb.x, 0.f);
                    float f3 = fmaxf(c[q][3] + bb.y, 0.f);
                    splitpack(f0, f1, a2h[j][hf * 2 + 0], a2l[j][hf * 2 + 0]);
                    splitpack(f2, f3, a2h[j][hf * 2 + 1], a2l[j][hf * 2 + 1]);
                }
            }

            // ---- GEMM2: [16,128] x [128,64]; half-groups of 4, merged uint4 B loads ----
            float c2[8][4];
#pragma unroll
            for (int ntq = 0; ntq < 8; ntq++)
#pragma unroll
                for (int q = 0; q < 4; q++) c2[ntq][q] = 0.f;
#pragma unroll
            for (int kc = 0; kc < 8; kc++) {
#pragma unroll
                for (int hg = 0; hg < 2; hg++) {
                    uint4 f[4];
#pragma unroll
                    for (int q = 0; q < 4; q++)
                        f[q] = sB2f[(kc * 8 + hg * 4 + q) * 32 + lane];
#pragma unroll
                    for (int q = 0; q < 4; q++) mma_bf16(c2[hg * 4 + q], a2h[kc], f[q].x, f[q].y);
#pragma unroll
                    for (int q = 0; q < 4; q++) mma_bf16(c2[hg * 4 + q], a2l[kc], f[q].x, f[q].y);
#pragma unroll
                    for (int q = 0; q < 4; q++) mma_bf16(c2[hg * 4 + q], a2h[kc], f[q].z, f[q].w);
                }
            }

            // ---- epilogue2 -> A3 fragments (4 kc) ----
            uint32_t a3h[4][4], a3l[4][4];
#pragma unroll
            for (int j = 0; j < 4; j++) {
#pragma unroll
                for (int hf = 0; hf < 2; hf++) {
                    int ntq = 2 * j + hf;
                    int col = ntq * 8 + (lane & 3) * 2;
                    float2 bb = *(const float2*)(sb2 + col);
                    float f0 = fmaxf(c2[ntq][0] + bb.x, 0.f);
                    float f1 = fmaxf(c2[ntq][1] + bb.y, 0.f);
                    float f2 = fmaxf(c2[ntq][2] + bb.x, 0.f);
                    float f3 = fmaxf(c2[ntq][3] + bb.y, 0.f);
                    splitpack(f0, f1, a3h[j][hf * 2 + 0], a3l[j][hf * 2 + 0]);
                    splitpack(f2, f3, a3h[j][hf * 2 + 1], a3l[j][hf * 2 + 1]);
                }
            }

            // ---- GEMM3: [16,64] x [64,32]; merged uint4 B loads ----
            float c3[4][4];
#pragma unroll
            for (int ntq = 0; ntq < 4; ntq++)
#pragma unroll
                for (int q = 0; q < 4; q++) c3[ntq][q] = 0.f;
#pragma unroll
            for (int kc = 0; kc < 4; kc++) {
                uint4 f[4];
#pragma unroll
                for (int q = 0; q < 4; q++)
                    f[q] = sB3f[(kc * 4 + q) * 32 + lane];
#pragma unroll
                for (int q = 0; q < 4; q++) mma_bf16(c3[q], a3h[kc], f[q].x, f[q].y);
#pragma unroll
                for (int q = 0; q < 4; q++) mma_bf16(c3[q], a3l[kc], f[q].x, f[q].y);
#pragma unroll
                for (int q = 0; q < 4; q++) mma_bf16(c3[q], a3h[kc], f[q].z, f[q].w);
            }

            // ---- layer4: relu(c3+b3) . w4, reduce across quad ----
            float p0 = 0.f, p1 = 0.f;
#pragma unroll
            for (int ntq = 0; ntq < 4; ntq++) {
                int col = ntq * 8 + (lane & 3) * 2;
                float2 bb = *(const float2*)(sb3 + col);
                float2 ww = *(const float2*)(sw4 + col);
                p0 = fmaf(fmaxf(c3[ntq][0] + bb.x, 0.f), ww.x, p0);
                p0 = fmaf(fmaxf(c3[ntq][1] + bb.y, 0.f), ww.y, p0);
                p1 = fmaf(fmaxf(c3[ntq][2] + bb.x, 0.f), ww.x, p1);
                p1 = fmaf(fmaxf(c3[ntq][3] + bb.y, 0.f), ww.y, p1);
            }
            p0 += __shfl_xor_sync(0xFFFFFFFFu, p0, 1);
            p0 += __shfl_xor_sync(0xFFFFFFFFu, p0, 2);
            p1 += __shfl_xor_sync(0xFFFFFFFFu, p1, 1);
            p1 += __shfl_xor_sync(0xFFFFFFFFu, p1, 2);
            if ((lane & 3) == 0) {
                int gr = tile * NTHREADS + rbase + (lane >> 2);
                if (gr < n)     out[gr]     = p0 + b4s;
                if (gr + 8 < n) out[gr + 8] = p1 + b4s;
            }
        }
    }
}

extern "C" void kernel_launch(void* const* d_in, const int* in_sizes, int n_in,
                              void* d_out, int out_size)
{
    const float* x    = (const float*)d_in[0];
    const float* W_ih = (const float*)d_in[1];
    const float* W_hh = (const float*)d_in[2];
    const float* b_ih = (const float*)d_in[3];
    const float* b_hh = (const float*)d_in[4];
    const float* W1   = (const float*)d_in[5];
    const float* b1   = (const float*)d_in[6];
    const float* W2   = (const float*)d_in[7];
    const float* b2   = (const float*)d_in[8];
    const float* W3   = (const float*)d_in[9];
    const float* b3   = (const float*)d_in[10];
    const float* W4   = (const float*)d_in[11];
    const float* b4   = (const float*)d_in[12];
    float* out = (float*)d_out;

    static bool attr_set = false;
    if (!attr_set) {
        cudaFuncSetAttribute(lstm_mlp_mma_kernel,
                             cudaFuncAttributeMaxDynamicSharedMemorySize, SMEM_BYTES);
        attr_set = true;
    }

    lstm_mlp_mma_kernel<<<NBLOCKS, NTHREADS, SMEM_BYTES>>>(
        x, W_ih, W_hh, b_ih, b_hh, W1, b1, W2, b2, W3, b3, W4, b4,
        out, out_size);
}

// round 16
// speedup vs baseline: 1.0775x; 1.0775x over previous
#include <cuda_runtime.h>
#include <cstdint>

typedef unsigned long long u64;

#define NTHREADS 256
#define NBLOCKS  (148 * 2)
#define HSTRIDE  20   // h row stride in words -> conflict-free A loads

// ---------------- SMEM byte offsets ----------------
#define OB_B1H   0        // W1 B-frags hi: 32 frags * 32 lanes * 8B = 8192
#define OB_B1L   8192
#define OB_B2H   16384    // W2: 64 frags = 16384
#define OB_B2L   32768
#define OB_B3H   49152    // W3: 16 frags = 4096
#define OB_B3L   53248
#define OB_HHI   57344    // h hi words: 256 rows * 20 w * 4B = 20480
#define OB_HLO   77824
#define OB_b1    98304    // 128 f
#define OB_b2    98816    // 64 f
#define OB_b3    99072    // 32 f
#define OB_w4    99200    // 32 f
#define OB_b4    99328
#define OB_wih   99332    // 32 f
#define OB_whh   99460    // 16 f
#define OB_bias  99524    // 8 f
#define SMEM_BYTES 99584

// ---------------- helpers ----------------
__device__ __forceinline__ u64 fma2(u64 a, u64 b, u64 c) {
    u64 d;
    asm("fma.rn.f32x2 %0, %1, %2, %3;" : "=l"(d) : "l"(a), "l"(b), "l"(c));
    return d;
}
__device__ __forceinline__ u64 pack2(float lo, float hi) {
    u64 d;
    asm("mov.b64 %0, {%1, %2};" : "=l"(d) : "f"(lo), "f"(hi));
    return d;
}
__device__ __forceinline__ void unpack2(u64 v, float& lo, float& hi) {
    asm("mov.b64 {%0, %1}, %2;" : "=f"(lo), "=f"(hi) : "l"(v));
}
__device__ __forceinline__ u64 bcast(float x) { return pack2(x, x); }

// split (a,b) -> hi word (truncated bf16 pair, a low) + lo word (RN residuals)
__device__ __forceinline__ void splitpack(float a, float b, uint32_t& hi, uint32_t& lo) {
    uint32_t ua = __float_as_uint(a), ub = __float_as_uint(b);
    asm("prmt.b32 %0, %1, %2, 0x7632;" : "=r"(hi) : "r"(ua), "r"(ub));
    float ra = a - __uint_as_float(ua & 0xFFFF0000u);
    float rb = b - __uint_as_float(ub & 0xFFFF0000u);
    asm("cvt.rn.bf16x2.f32 %0, %1, %2;" : "=r"(lo) : "f"(rb), "f"(ra));
}
__device__ __forceinline__ void mma_bf16(float* c, const uint32_t* a, uint2 b) {
    asm volatile(
        "mma.sync.aligned.m16n8k16.row.col.f32.bf16.bf16.f32 "
        "{%0,%1,%2,%3}, {%4,%5,%6,%7}, {%8,%9}, {%0,%1,%2,%3};"
        : "+f"(c[0]), "+f"(c[1]), "+f"(c[2]), "+f"(c[3])
        : "r"(a[0]), "r"(a[1]), "r"(a[2]), "r"(a[3]), "r"(b.x), "r"(b.y));
}
__device__ __forceinline__ float sigf(float x) {
    float e = __expf(-x);
    return __fdividef(1.0f, 1.0f + e);
}
__device__ __forceinline__ float tanhfast(float x) {
    float e = __expf(-2.0f * x);
    return __fdividef(2.0f, 1.0f + e) - 1.0f;
}

__global__ void __launch_bounds__(NTHREADS, 2)
lstm_mlp_mma_kernel(const float* __restrict__ x,
                    const float* __restrict__ W_ih, const float* __restrict__ W_hh,
                    const float* __restrict__ b_ih, const float* __restrict__ b_hh,
                    const float* __restrict__ W1, const float* __restrict__ b1,
                    const float* __restrict__ W2, const float* __restrict__ b2,
                    const float* __restrict__ W3, const float* __restrict__ b3,
                    const float* __restrict__ W4, const float* __restrict__ b4,
                    float* __restrict__ out, int n)
{
    extern __shared__ char smem[];
    const int tid  = threadIdx.x;
    const int lane = tid & 31;

    uint2* sB1h = (uint2*)(smem + OB_B1H);
    uint2* sB1l = (uint2*)(smem + OB_B1L);
    uint2* sB2h = (uint2*)(smem + OB_B2H);
    uint2* sB2l = (uint2*)(smem + OB_B2L);
    uint2* sB3h = (uint2*)(smem + OB_B3H);
    uint2* sB3l = (uint2*)(smem + OB_B3L);
    uint32_t* hH = (uint32_t*)(smem + OB_HHI);
    uint32_t* hL = (uint32_t*)(smem + OB_HLO);
    float* sb1  = (float*)(smem + OB_b1);
    float* sb2  = (float*)(smem + OB_b2);
    float* sb3  = (float*)(smem + OB_b3);
    float* sw4  = (float*)(smem + OB_w4);
    float* sb4  = (float*)(smem + OB_b4);
    float* sWih = (float*)(smem + OB_wih);
    float* sWhh = (float*)(smem + OB_whh);
    float* sBias= (float*)(smem + OB_bias);

    // ---- stage small params ----
    if (tid < 128) sb1[tid] = b1[tid];
    if (tid < 64)  sb2[tid] = b2[tid];
    if (tid < 32)  { sb3[tid] = b3[tid]; sw4[tid] = W4[tid]; }
    if (tid == 0)  sb4[0] = b4[0];
    if (tid < 32)  sWih[tid] = W_ih[tid];
    if (tid < 16)  sWhh[tid] = W_hh[tid];
    if (tid < 8)   sBias[tid] = b_ih[tid] + b_hh[tid];

    // ---- precompute B fragments (native m16n8k16 col-major B layout) ----
    // W1 [128,20], K padded to 32: 2 kc x 16 nt
    for (int e = tid; e < 32 * 32; e += NTHREADS) {
        int l = e & 31, f = e >> 5;
        int kc = f >> 4, nt = f & 15;
        int col = nt * 8 + (l >> 2);
        int k0 = kc * 16 + (l & 3) * 2;
        float v00 = (k0     < 20) ? W1[col * 20 + k0]     : 0.f;
        float v01 = (k0 + 1 < 20) ? W1[col * 20 + k0 + 1] : 0.f;
        float v10 = (k0 + 8 < 20) ? W1[col * 20 + k0 + 8] : 0.f;
        float v11 = (k0 + 9 < 20) ? W1[col * 20 + k0 + 9] : 0.f;
        uint32_t h0, l0, h1, l1;
        splitpack(v00, v01, h0, l0);
        splitpack(v10, v11, h1, l1);
        sB1h[f * 32 + l] = make_uint2(h0, h1);
        sB1l[f * 32 + l] = make_uint2(l0, l1);
    }
    // W2 [64,128]: 8 kc x 8 nt
    for (int e = tid; e < 64 * 32; e += NTHREADS) {
        int l = e & 31, f = e >> 5;
        int kc = f >> 3, nt = f & 7;
        int col = nt * 8 + (l >> 2);
        int k0 = kc * 16 + (l & 3) * 2;
        uint32_t h0, l0, h1, l1;
        splitpack(W2[col * 128 + k0],     W2[col * 128 + k0 + 1], h0, l0);
        splitpack(W2[col * 128 + k0 + 8], W2[col * 128 + k0 + 9], h1, l1);
        sB2h[f * 32 + l] = make_uint2(h0, h1);
        sB2l[f * 32 + l] = make_uint2(l0, l1);
    }
    // W3 [32,64]: 4 kc x 4 nt
    for (int e = tid; e < 16 * 32; e += NTHREADS) {
        int l = e & 31, f = e >> 5;
        int kc = f >> 2, nt = f & 3;
        int col = nt * 8 + (l >> 2);
        int k0 = kc * 16 + (l & 3) * 2;
        uint32_t h0, l0, h1, l1;
        splitpack(W3[col * 64 + k0],     W3[col * 64 + k0 + 1], h0, l0);
        splitpack(W3[col * 64 + k0 + 8], W3[col * 64 + k0 + 9], h1, l1);
        sB3h[f * 32 + l] = make_uint2(h0, h1);
        sB3l[f * 32 + l] = make_uint2(l0, l1);
    }
    // zero K-pad words of h arrays (cols 20..31 -> words 10..15), constant across tiles
#pragma unroll
    for (int w = 10; w < 16; w++) {
        hH[tid * HSTRIDE + w] = 0u;
        hL[tid * HSTRIDE + w] = 0u;
    }
    __syncthreads();

    const float b4s = sb4[0];

    const int ntiles = (n + NTHREADS - 1) / NTHREADS;
    for (int tile = blockIdx.x; tile < ntiles; tile += gridDim.x) {
        const int row = tile * NTHREADS + tid;
        const bool valid = (row < n);

        // ================= LSTM (1 element/thread, packed f32x2 gate pairs) =================
        // Weights loaded from SMEM per tile (per-tile lifetime: dead before GEMM peak).
        {
            u64 rwih2[16], rwhh2[8], rbias2[4];
#pragma unroll
            for (int p = 0; p < 4; p++) {
#pragma unroll
                for (int k = 0; k < 4; k++)
                    rwih2[p * 4 + k] = pack2(sWih[(2 * p) * 4 + k], sWih[(2 * p + 1) * 4 + k]);
#pragma unroll
                for (int k = 0; k < 2; k++)
                    rwhh2[p * 2 + k] = pack2(sWhh[(2 * p) * 2 + k], sWhh[(2 * p + 1) * 2 + k]);
                rbias2[p] = pack2(sBias[2 * p], sBias[2 * p + 1]);
            }

            float h0 = 0.f, h1 = 0.f, c0 = 0.f, c1 = 0.f;
            const float* xp = x + (size_t)(valid ? row : 0) * 40;
#pragma unroll
            for (int t = 0; t < 10; t++) {
                float4 xt = *reinterpret_cast<const float4*>(xp + t * 4);
                u64 bx0 = bcast(xt.x), bx1 = bcast(xt.y);
                u64 bx2 = bcast(xt.z), bx3 = bcast(xt.w);
                u64 bh0 = bcast(h0),   bh1 = bcast(h1);
                float g[8];
#pragma unroll
                for (int p = 0; p < 4; p++) {
                    u64 a = rbias2[p];
                    a = fma2(bx0, rwih2[p * 4 + 0], a);
                    a = fma2(bx1, rwih2[p * 4 + 1], a);
                    a = fma2(bx2, rwih2[p * 4 + 2], a);
                    a = fma2(bx3, rwih2[p * 4 + 3], a);
                    a = fma2(bh0, rwhh2[p * 2 + 0], a);
                    a = fma2(bh1, rwhh2[p * 2 + 1], a);
                    unpack2(a, g[2 * p], g[2 * p + 1]);
                }
                float i0 = sigf(g[0]), i1 = sigf(g[1]);
                float f0 = sigf(g[2]), f1 = sigf(g[3]);
                float g0 = tanhfast(g[4]), g1 = tanhfast(g[5]);
                float o0 = sigf(g[6]), o1 = sigf(g[7]);
                c0 = fmaf(f0, c0, i0 * g0);
                c1 = fmaf(f1, c1, i1 * g1);
                h0 = o0 * tanhfast(c0);
                h1 = o1 * tanhfast(c1);
                uint32_t wh, wl;
                splitpack(h0, h1, wh, wl);
                hH[tid * HSTRIDE + t] = wh;
                hL[tid * HSTRIDE + t] = wl;
            }
        }
        __syncwarp();

        // ================= MLP on tensor cores, per warp, 2 sub-tiles =================
#pragma unroll 1
        for (int s = 0; s < 2; s++) {
            const int rbase = (tid >> 5) * 32 + s * 16;
            const int r0 = rbase + (lane >> 2);

            // ---- A1 fragments for both kc (conflict-free stride-20 loads) ----
            uint32_t ah[2][4], al[2][4];
#pragma unroll
            for (int kc = 0; kc < 2; kc++) {
                const int wofs = kc * 8 + (lane & 3);
                ah[kc][0] = hH[r0 * HSTRIDE + wofs];
                ah[kc][1] = hH[(r0 + 8) * HSTRIDE + wofs];
                ah[kc][2] = hH[r0 * HSTRIDE + wofs + 4];
                ah[kc][3] = hH[(r0 + 8) * HSTRIDE + wofs + 4];
                al[kc][0] = hL[r0 * HSTRIDE + wofs];
                al[kc][1] = hL[(r0 + 8) * HSTRIDE + wofs];
                al[kc][2] = hL[r0 * HSTRIDE + wofs + 4];
                al[kc][3] = hL[(r0 + 8) * HSTRIDE + wofs + 4];
            }

            // ---- GEMM1 (groups of 4 n-tiles, interleaved mma) + fused epilogue1 ----
            uint32_t a2h[8][4], a2l[8][4];
#pragma unroll
            for (int g = 0; g < 4; g++) {
                float c[4][4];
#pragma unroll
                for (int q = 0; q < 4; q++)
#pragma unroll
                    for (int e = 0; e < 4; e++) c[q][e] = 0.f;
#pragma unroll
                for (int kc = 0; kc < 2; kc++) {
                    uint2 bh[4], bl[4];
#pragma unroll
                    for (int q = 0; q < 4; q++) {
                        bh[q] = sB1h[(kc * 16 + 4 * g + q) * 32 + lane];
                        bl[q] = sB1l[(kc * 16 + 4 * g + q) * 32 + lane];
                    }
#pragma unroll
                    for (int q = 0; q < 4; q++) mma_bf16(c[q], ah[kc], bh[q]);
#pragma unroll
                    for (int q = 0; q < 4; q++) mma_bf16(c[q], al[kc], bh[q]);
#pragma unroll
                    for (int q = 0; q < 4; q++) mma_bf16(c[q], ah[kc], bl[q]);
                }
                // epilogue1 for these 4 n-tiles
#pragma unroll
                for (int q = 0; q < 4; q++) {
                    const int ntq = 4 * g + q;
                    const int j = ntq >> 1, hf = ntq & 1;
                    int col = ntq * 8 + (lane & 3) * 2;
                    float2 bb = *(const float2*)(sb1 + col);
                    float f0 = fmaxf(c[q][0] + bb.x, 0.f);
                    float f1 = fmaxf(c[q][1] + bb.y, 0.f);
                    float f2 = fmaxf(c[q][2] + bb.x, 0.f);
                    float f3 = fmaxf(c[q][3] + bb.y, 0.f);
                    splitpack(f0, f1, a2h[j][hf * 2 + 0], a2l[j][hf * 2 + 0]);
                    splitpack(f2, f3, a2h[j][hf * 2 + 1], a2l[j][hf * 2 + 1]);
                }
            }

            // ---- GEMM2: [16,128] x [128,64]; term-major, 8-way interleave ----
            float c2[8][4];
#pragma unroll
            for (int ntq = 0; ntq < 8; ntq++)
#pragma unroll
                for (int q = 0; q < 4; q++) c2[ntq][q] = 0.f;
#pragma unroll
            for (int kc = 0; kc < 8; kc++) {
                uint2 bh[8];
#pragma unroll
                for (int q = 0; q < 8; q++) bh[q] = sB2h[(kc * 8 + q) * 32 + lane];
#pragma unroll
                for (int q = 0; q < 8; q++) mma_bf16(c2[q], a2h[kc], bh[q]);
#pragma unroll
                for (int q = 0; q < 8; q++) mma_bf16(c2[q], a2l[kc], bh[q]);
#pragma unroll
                for (int q = 0; q < 8; q++) {
                    uint2 bl = sB2l[(kc * 8 + q) * 32 + lane];
                    mma_bf16(c2[q], a2h[kc], bl);
                }
            }

            // ---- epilogue2 -> A3 fragments (4 kc) ----
            uint32_t a3h[4][4], a3l[4][4];
#pragma unroll
            for (int j = 0; j < 4; j++) {
#pragma unroll
                for (int hf = 0; hf < 2; hf++) {
                    int ntq = 2 * j + hf;
                    int col = ntq * 8 + (lane & 3) * 2;
                    float2 bb = *(const float2*)(sb2 + col);
                    float f0 = fmaxf(c2[ntq][0] + bb.x, 0.f);
                    float f1 = fmaxf(c2[ntq][1] + bb.y, 0.f);
                    float f2 = fmaxf(c2[ntq][2] + bb.x, 0.f);
                    float f3 = fmaxf(c2[ntq][3] + bb.y, 0.f);
                    splitpack(f0, f1, a3h[j][hf * 2 + 0], a3l[j][hf * 2 + 0]);
                    splitpack(f2, f3, a3h[j][hf * 2 + 1], a3l[j][hf * 2 + 1]);
                }
            }

            // ---- GEMM3: [16,64] x [64,32]; term-major, 4-way interleave ----
            float c3[4][4];
#pragma unroll
            for (int ntq = 0; ntq < 4; ntq++)
#pragma unroll
                for (int q = 0; q < 4; q++) c3[ntq][q] = 0.f;
#pragma unroll
            for (int kc = 0; kc < 4; kc++) {
                uint2 bh[4];
#pragma unroll
                for (int q = 0; q < 4; q++) bh[q] = sB3h[(kc * 4 + q) * 32 + lane];
#pragma unroll
                for (int q = 0; q < 4; q++) mma_bf16(c3[q], a3h[kc], bh[q]);
#pragma unroll
                for (int q = 0; q < 4; q++) mma_bf16(c3[q], a3l[kc], bh[q]);
#pragma unroll
                for (int q = 0; q < 4; q++) {
                    uint2 bl = sB3l[(kc * 4 + q) * 32 + lane];
                    mma_bf16(c3[q], a3h[kc], bl);
                }
            }

            // ---- layer4: relu(c3+b3) . w4, reduce across quad ----
            float p0 = 0.f, p1 = 0.f;
#pragma unroll
            for (int ntq = 0; ntq < 4; ntq++) {
                int col = ntq * 8 + (lane & 3) * 2;
                float2 bb = *(const float2*)(sb3 + col);
                float2 ww = *(const float2*)(sw4 + col);
                p0 = fmaf(fmaxf(c3[ntq][0] + bb.x, 0.f), ww.x, p0);
                p0 = fmaf(fmaxf(c3[ntq][1] + bb.y, 0.f), ww.y, p0);
                p1 = fmaf(fmaxf(c3[ntq][2] + bb.x, 0.f), ww.x, p1);
                p1 = fmaf(fmaxf(c3[ntq][3] + bb.y, 0.f), ww.y, p1);
            }
            p0 += __shfl_xor_sync(0xFFFFFFFFu, p0, 1);
            p0 += __shfl_xor_sync(0xFFFFFFFFu, p0, 2);
            p1 += __shfl_xor_sync(0xFFFFFFFFu, p1, 1);
            p1 += __shfl_xor_sync(0xFFFFFFFFu, p1, 2);
            if ((lane & 3) == 0) {
                int gr = tile * NTHREADS + rbase + (lane >> 2);
                if (gr < n)     out[gr]     = p0 + b4s;
                if (gr + 8 < n) out[gr + 8] = p1 + b4s;
            }
        }
    }
}

extern "C" void kernel_launch(void* const* d_in, const int* in_sizes, int n_in,
                              void* d_out, int out_size)
{
    const float* x    = (const float*)d_in[0];
    const float* W_ih = (const float*)d_in[1];
    const float* W_hh = (const float*)d_in[2];
    const float* b_ih = (const float*)d_in[3];
    const float* b_hh = (const float*)d_in[4];
    const float* W1   = (const float*)d_in[5];
    const float* b1   = (const float*)d_in[6];
    const float* W2   = (const float*)d_in[7];
    const float* b2   = (const float*)d_in[8];
    const float* W3   = (const float*)d_in[9];
    const float* b3   = (const float*)d_in[10];
    const float* W4   = (const float*)d_in[11];
    const float* b4   = (const float*)d_in[12];
    float* out = (float*)d_out;

    static bool attr_set = false;
    if (!attr_set) {
        cudaFuncSetAttribute(lstm_mlp_mma_kernel,
                             cudaFuncAttributeMaxDynamicSharedMemorySize, SMEM_BYTES);
        attr_set = true;
    }

    lstm_mlp_mma_kernel<<<NBLOCKS, NTHREADS, SMEM_BYTES>>>(
        x, W_ih, W_hh, b_ih, b_hh, W1, b1, W2, b2, W3, b3, W4, b4,
        out, out_size);
}

// round 17
// speedup vs baseline: 1.1408x; 1.0588x over previous
#include <cuda_runtime.h>
#include <cstdint>

#define NTHREADS 256
#define NBLOCKS  (148 * 2)
#define HSTRIDE  20   // h row stride in words -> conflict-free A loads

// ---------------- SMEM byte offsets ----------------
#define OB_B1H   0        // W1 k16 B-frags hi: 16 frags * 32 * 8B = 4096
#define OB_B1L   4096
#define OB_B1H8  8192     // W1 k8 B-frags hi: 16 frags * 32 * 4B = 2048
#define OB_B1L8  10240
#define OB_B2H   12288    // W2: 64 frags * 32 * 8B = 16384
#define OB_B2L   28672
#define OB_B3H   45056    // W3: 16 frags = 4096
#define OB_B3L   49152
#define OB_HHI   53248    // h hi words: 256 rows * 20 w * 4B = 20480
#define OB_HLO   73728
#define OB_b1    94208    // 128 f
#define OB_b2    94720    // 64 f
#define OB_b3    94976    // 32 f
#define OB_w4    95104    // 32 f
#define OB_b4    95232
#define OB_wih   95236    // 32 f
#define OB_whh   95364    // 16 f
#define OB_bias  95428    // 8 f
#define SMEM_BYTES 95488

// ---------------- helpers ----------------
// split (a,b) -> hi word (truncated bf16 pair, a low) + lo word (RN residuals)
__device__ __forceinline__ void splitpack(float a, float b, uint32_t& hi, uint32_t& lo) {
    uint32_t ua = __float_as_uint(a), ub = __float_as_uint(b);
    asm("prmt.b32 %0, %1, %2, 0x7632;" : "=r"(hi) : "r"(ua), "r"(ub));
    float ra = a - __uint_as_float(ua & 0xFFFF0000u);
    float rb = b - __uint_as_float(ub & 0xFFFF0000u);
    asm("cvt.rn.bf16x2.f32 %0, %1, %2;" : "=r"(lo) : "f"(rb), "f"(ra));
}
__device__ __forceinline__ void mma_bf16(float* c, const uint32_t* a, uint2 b) {
    asm volatile(
        "mma.sync.aligned.m16n8k16.row.col.f32.bf16.bf16.f32 "
        "{%0,%1,%2,%3}, {%4,%5,%6,%7}, {%8,%9}, {%0,%1,%2,%3};"
        : "+f"(c[0]), "+f"(c[1]), "+f"(c[2]), "+f"(c[3])
        : "r"(a[0]), "r"(a[1]), "r"(a[2]), "r"(a[3]), "r"(b.x), "r"(b.y));
}
__device__ __forceinline__ void mma_bf16_k8(float* c, const uint32_t* a, uint32_t b) {
    asm volatile(
        "mma.sync.aligned.m16n8k8.row.col.f32.bf16.bf16.f32 "
        "{%0,%1,%2,%3}, {%4,%5}, {%6}, {%0,%1,%2,%3};"
        : "+f"(c[0]), "+f"(c[1]), "+f"(c[2]), "+f"(c[3])
        : "r"(a[0]), "r"(a[1]), "r"(b));
}
__device__ __forceinline__ float sigf(float x) {
    float e = __expf(-x);
    return __fdividef(1.0f, 1.0f + e);
}
__device__ __forceinline__ float tanhfast(float x) {
    float e = __expf(-2.0f * x);
    return __fdividef(2.0f, 1.0f + e) - 1.0f;
}

__global__ void __launch_bounds__(NTHREADS, 2)
lstm_mlp_mma_kernel(const float* __restrict__ x,
                    const float* __restrict__ W_ih, const float* __restrict__ W_hh,
                    const float* __restrict__ b_ih, const float* __restrict__ b_hh,
                    const float* __restrict__ W1, const float* __restrict__ b1,
                    const float* __restrict__ W2, const float* __restrict__ b2,
                    const float* __restrict__ W3, const float* __restrict__ b3,
                    const float* __restrict__ W4, const float* __restrict__ b4,
                    float* __restrict__ out, int n)
{
    extern __shared__ char smem[];
    const int tid  = threadIdx.x;
    const int lane = tid & 31;

    uint2* sB1h = (uint2*)(smem + OB_B1H);
    uint2* sB1l = (uint2*)(smem + OB_B1L);
    uint32_t* sB1h8 = (uint32_t*)(smem + OB_B1H8);
    uint32_t* sB1l8 = (uint32_t*)(smem + OB_B1L8);
    uint2* sB2h = (uint2*)(smem + OB_B2H);
    uint2* sB2l = (uint2*)(smem + OB_B2L);
    uint2* sB3h = (uint2*)(smem + OB_B3H);
    uint2* sB3l = (uint2*)(smem + OB_B3L);
    uint32_t* hH = (uint32_t*)(smem + OB_HHI);
    uint32_t* hL = (uint32_t*)(smem + OB_HLO);
    float* sb1  = (float*)(smem + OB_b1);
    float* sb2  = (float*)(smem + OB_b2);
    float* sb3  = (float*)(smem + OB_b3);
    float* sw4  = (float*)(smem + OB_w4);
    float* sb4  = (float*)(smem + OB_b4);
    float* sWih = (float*)(smem + OB_wih);
    float* sWhh = (float*)(smem + OB_whh);
    float* sBias= (float*)(smem + OB_bias);

    // ---- stage small params ----
    if (tid < 128) sb1[tid] = b1[tid];
    if (tid < 64)  sb2[tid] = b2[tid];
    if (tid < 32)  { sb3[tid] = b3[tid]; sw4[tid] = W4[tid]; }
    if (tid == 0)  sb4[0] = b4[0];
    if (tid < 32)  sWih[tid] = W_ih[tid];
    if (tid < 16)  sWhh[tid] = W_hh[tid];
    if (tid < 8)   sBias[tid] = b_ih[tid] + b_hh[tid];

    // ---- precompute B fragments (native mma col-major B layouts) ----
    // W1 k16 chunk (k0..15): 16 nt
    for (int e = tid; e < 16 * 32; e += NTHREADS) {
        int l = e & 31, nt = e >> 5;
        int col = nt * 8 + (l >> 2);
        int k0 = (l & 3) * 2;
        uint32_t h0, l0, h1, l1;
        splitpack(W1[col * 20 + k0],     W1[col * 20 + k0 + 1], h0, l0);
        splitpack(W1[col * 20 + k0 + 8], W1[col * 20 + k0 + 9], h1, l1);
        sB1h[nt * 32 + l] = make_uint2(h0, h1);
        sB1l[nt * 32 + l] = make_uint2(l0, l1);
    }
    // W1 k8 chunk (k16..23, pad >=20): 16 nt, 1 word/lane
    for (int e = tid; e < 16 * 32; e += NTHREADS) {
        int l = e & 31, nt = e >> 5;
        int col = nt * 8 + (l >> 2);
        int k0 = 16 + (l & 3) * 2;
        float v0 = (k0     < 20) ? W1[col * 20 + k0]     : 0.f;
        float v1 = (k0 + 1 < 20) ? W1[col * 20 + k0 + 1] : 0.f;
        uint32_t h0, l0;
        splitpack(v0, v1, h0, l0);
        sB1h8[nt * 32 + l] = h0;
        sB1l8[nt * 32 + l] = l0;
    }
    // W2 [64,128]: 8 kc x 8 nt
    for (int e = tid; e < 64 * 32; e += NTHREADS) {
        int l = e & 31, f = e >> 5;
        int kc = f >> 3, nt = f & 7;
        int col = nt * 8 + (l >> 2);
        int k0 = kc * 16 + (l & 3) * 2;
        uint32_t h0, l0, h1, l1;
        splitpack(W2[col * 128 + k0],     W2[col * 128 + k0 + 1], h0, l0);
        splitpack(W2[col * 128 + k0 + 8], W2[col * 128 + k0 + 9], h1, l1);
        sB2h[f * 32 + l] = make_uint2(h0, h1);
        sB2l[f * 32 + l] = make_uint2(l0, l1);
    }
    // W3 [32,64]: 4 kc x 4 nt
    for (int e = tid; e < 16 * 32; e += NTHREADS) {
        int l = e & 31, f = e >> 5;
        int kc = f >> 2, nt = f & 3;
        int col = nt * 8 + (l >> 2);
        int k0 = kc * 16 + (l & 3) * 2;
        uint32_t h0, l0, h1, l1;
        splitpack(W3[col * 64 + k0],     W3[col * 64 + k0 + 1], h0, l0);
        splitpack(W3[col * 64 + k0 + 8], W3[col * 64 + k0 + 9], h1, l1);
        sB3h[f * 32 + l] = make_uint2(h0, h1);
        sB3l[f * 32 + l] = make_uint2(l0, l1);
    }
    // zero K-pad words (10..11: k20..23 of the k8 chunk), constant across tiles
#pragma unroll
    for (int w = 10; w < 12; w++) {
        hH[tid * HSTRIDE + w] = 0u;
        hL[tid * HSTRIDE + w] = 0u;
    }
    __syncthreads();

    const float b4s = sb4[0];

    const int ntiles = (n + NTHREADS - 1) / NTHREADS;
    for (int tile = blockIdx.x; tile < ntiles; tile += gridDim.x) {
        const int row = tile * NTHREADS + tid;
        const bool valid = (row < n);

        // ================= LSTM (1 element/thread) =================
        // LSTM weights loaded from SMEM per tile (per-tile lifetime).
        {
            float rwih[32], rwhh[16], rbias[8];
#pragma unroll
            for (int i = 0; i < 32; i++) rwih[i] = sWih[i];
#pragma unroll
            for (int i = 0; i < 16; i++) rwhh[i] = sWhh[i];
#pragma unroll
            for (int i = 0; i < 8; i++)  rbias[i] = sBias[i];

            float h0 = 0.f, h1 = 0.f, c0 = 0.f, c1 = 0.f;
            const float* xp = x + (size_t)(valid ? row : 0) * 40;
#pragma unroll
            for (int t = 0; t < 10; t++) {
                float4 xt = *reinterpret_cast<const float4*>(xp + t * 4);
                float g[8];
#pragma unroll
                for (int gi = 0; gi < 8; gi++) {
                    float a = rbias[gi];
                    a = fmaf(xt.x, rwih[gi * 4 + 0], a);
                    a = fmaf(xt.y, rwih[gi * 4 + 1], a);
                    a = fmaf(xt.z, rwih[gi * 4 + 2], a);
                    a = fmaf(xt.w, rwih[gi * 4 + 3], a);
                    a = fmaf(h0, rwhh[gi * 2 + 0], a);
                    a = fmaf(h1, rwhh[gi * 2 + 1], a);
                    g[gi] = a;
                }
                float i0 = sigf(g[0]), i1 = sigf(g[1]);
                float f0 = sigf(g[2]), f1 = sigf(g[3]);
                float g0 = tanhfast(g[4]), g1 = tanhfast(g[5]);
                float o0 = sigf(g[6]), o1 = sigf(g[7]);
                c0 = fmaf(f0, c0, i0 * g0);
                c1 = fmaf(f1, c1, i1 * g1);
                h0 = o0 * tanhfast(c0);
                h1 = o1 * tanhfast(c1);
                uint32_t wh, wl;
                splitpack(h0, h1, wh, wl);
                hH[tid * HSTRIDE + t] = wh;
                hL[tid * HSTRIDE + t] = wl;
            }
        }
        __syncwarp();

        // ================= MLP on tensor cores, per warp, 2 sub-tiles =================
#pragma unroll 1
        for (int s = 0; s < 2; s++) {
            const int rbase = (tid >> 5) * 32 + s * 16;
            const int r0 = rbase + (lane >> 2);

            // ---- A1 fragments: k16 chunk (words 0..7) + k8 chunk (words 8..9 + pad 10..11) ----
            uint32_t ah0[4], al0[4], ah8[2], al8[2];
            {
                const int w16 = lane & 3;
                ah0[0] = hH[r0 * HSTRIDE + w16];
                ah0[1] = hH[(r0 + 8) * HSTRIDE + w16];
                ah0[2] = hH[r0 * HSTRIDE + w16 + 4];
                ah0[3] = hH[(r0 + 8) * HSTRIDE + w16 + 4];
                al0[0] = hL[r0 * HSTRIDE + w16];
                al0[1] = hL[(r0 + 8) * HSTRIDE + w16];
                al0[2] = hL[r0 * HSTRIDE + w16 + 4];
                al0[3] = hL[(r0 + 8) * HSTRIDE + w16 + 4];
                ah8[0] = hH[r0 * HSTRIDE + w16 + 8];
                ah8[1] = hH[(r0 + 8) * HSTRIDE + w16 + 8];
                al8[0] = hL[r0 * HSTRIDE + w16 + 8];
                al8[1] = hL[(r0 + 8) * HSTRIDE + w16 + 8];
            }

            // ---- GEMM1 (groups of 4 n-tiles, k16 + k8 chunks) + fused epilogue1 ----
            uint32_t a2h[8][4], a2l[8][4];
#pragma unroll
            for (int g = 0; g < 4; g++) {
                float c[4][4];
#pragma unroll
                for (int q = 0; q < 4; q++)
#pragma unroll
                    for (int e = 0; e < 4; e++) c[q][e] = 0.f;
                // k16 chunk (k0..15)
                {
                    uint2 bh[4], bl[4];
#pragma unroll
                    for (int q = 0; q < 4; q++) {
                        bh[q] = sB1h[(4 * g + q) * 32 + lane];
                        bl[q] = sB1l[(4 * g + q) * 32 + lane];
                    }
#pragma unroll
                    for (int q = 0; q < 4; q++) mma_bf16(c[q], ah0, bh[q]);
#pragma unroll
                    for (int q = 0; q < 4; q++) mma_bf16(c[q], al0, bh[q]);
#pragma unroll
                    for (int q = 0; q < 4; q++) mma_bf16(c[q], ah0, bl[q]);
                }
                // k8 chunk (k16..19 + pad)
                {
                    uint32_t bh8[4], bl8[4];
#pragma unroll
                    for (int q = 0; q < 4; q++) {
                        bh8[q] = sB1h8[(4 * g + q) * 32 + lane];
                        bl8[q] = sB1l8[(4 * g + q) * 32 + lane];
                    }
#pragma unroll
                    for (int q = 0; q < 4; q++) mma_bf16_k8(c[q], ah8, bh8[q]);
#pragma unroll
                    for (int q = 0; q < 4; q++) mma_bf16_k8(c[q], al8, bh8[q]);
#pragma unroll
                    for (int q = 0; q < 4; q++) mma_bf16_k8(c[q], ah8, bl8[q]);
                }
                // epilogue1 for these 4 n-tiles
#pragma unroll
                for (int q = 0; q < 4; q++) {
                    const int ntq = 4 * g + q;
                    const int j = ntq >> 1, hf = ntq & 1;
                    int col = ntq * 8 + (lane & 3) * 2;
                    float2 bb = *(const float2*)(sb1 + col);
                    float f0 = fmaxf(c[q][0] + bb.x, 0.f);
                    float f1 = fmaxf(c[q][1] + bb.y, 0.f);
                    float f2 = fmaxf(c[q][2] + bb.x, 0.f);
                    float f3 = fmaxf(c[q][3] + bb.y, 0.f);
                    splitpack(f0, f1, a2h[j][hf * 2 + 0], a2l[j][hf * 2 + 0]);
                    splitpack(f2, f3, a2h[j][hf * 2 + 1], a2l[j][hf * 2 + 1]);
                }
            }

            // ---- GEMM2: [16,128] x [128,64]; term-major, 8-way interleave ----
            float c2[8][4];
#pragma unroll
            for (int ntq = 0; ntq < 8; ntq++)
#pragma unroll
                for (int q = 0; q < 4; q++) c2[ntq][q] = 0.f;
#pragma unroll
            for (int kc = 0; kc < 8; kc++) {
                uint2 bh[8];
#pragma unroll
                for (int q = 0; q < 8; q++) bh[q] = sB2h[(kc * 8 + q) * 32 + lane];
#pragma unroll
                for (int q = 0; q < 8; q++) mma_bf16(c2[q], a2h[kc], bh[q]);
#pragma unroll
                for (int q = 0; q < 8; q++) mma_bf16(c2[q], a2l[kc], bh[q]);
#pragma unroll
                for (int q = 0; q < 8; q++) {
                    uint2 bl = sB2l[(kc * 8 + q) * 32 + lane];
                    mma_bf16(c2[q], a2h[kc], bl);
                }
            }

            // ---- epilogue2 -> A3 fragments (4 kc) ----
            uint32_t a3h[4][4], a3l[4][4];
#pragma unroll
            for (int j = 0; j < 4; j++) {
#pragma unroll
                for (int hf = 0; hf < 2; hf++) {
                    int ntq = 2 * j + hf;
                    int col = ntq * 8 + (lane & 3) * 2;
                    float2 bb = *(const float2*)(sb2 + col);
                    float f0 = fmaxf(c2[ntq][0] + bb.x, 0.f);
                    float f1 = fmaxf(c2[ntq][1] + bb.y, 0.f);
                    float f2 = fmaxf(c2[ntq][2] + bb.x, 0.f);
                    float f3 = fmaxf(c2[ntq][3] + bb.y, 0.f);
                    splitpack(f0, f1, a3h[j][hf * 2 + 0], a3l[j][hf * 2 + 0]);
                    splitpack(f2, f3, a3h[j][hf * 2 + 1], a3l[j][hf * 2 + 1]);
                }
            }

            // ---- GEMM3: [16,64] x [64,32]; term-major, 4-way interleave ----
            float c3[4][4];
#pragma unroll
            for (int ntq = 0; ntq < 4; ntq++)
#pragma unroll
                for (int q = 0; q < 4; q++) c3[ntq][q] = 0.f;
#pragma unroll
            for (int kc = 0; kc < 4; kc++) {
                uint2 bh[4];
#pragma unroll
                for (int q = 0; q < 4; q++) bh[q] = sB3h[(kc * 4 + q) * 32 + lane];
#pragma unroll
                for (int q = 0; q < 4; q++) mma_bf16(c3[q], a3h[kc], bh[q]);
#pragma unroll
                for (int q = 0; q < 4; q++) mma_bf16(c3[q], a3l[kc], bh[q]);
#pragma unroll
                for (int q = 0; q < 4; q++) {
                    uint2 bl = sB3l[(kc * 4 + q) * 32 + lane];
                    mma_bf16(c3[q], a3h[kc], bl);
                }
            }

            // ---- layer4: relu(c3+b3) . w4, reduce across quad ----
            float p0 = 0.f, p1 = 0.f;
#pragma unroll
            for (int ntq = 0; ntq < 4; ntq++) {
                int col = ntq * 8 + (lane & 3) * 2;
                float2 bb = *(const float2*)(sb3 + col);
                float2 ww = *(const float2*)(sw4 + col);
                p0 = fmaf(fmaxf(c3[ntq][0] + bb.x, 0.f), ww.x, p0);
                p0 = fmaf(fmaxf(c3[ntq][1] + bb.y, 0.f), ww.y, p0);
                p1 = fmaf(fmaxf(c3[ntq][2] + bb.x, 0.f), ww.x, p1);
                p1 = fmaf(fmaxf(c3[ntq][3] + bb.y, 0.f), ww.y, p1);
            }
            p0 += __shfl_xor_sync(0xFFFFFFFFu, p0, 1);
            p0 += __shfl_xor_sync(0xFFFFFFFFu, p0, 2);
            p1 += __shfl_xor_sync(0xFFFFFFFFu, p1, 1);
            p1 += __shfl_xor_sync(0xFFFFFFFFu, p1, 2);
            if ((lane & 3) == 0) {
                int gr = tile * NTHREADS + rbase + (lane >> 2);
                if (gr < n)     out[gr]     = p0 + b4s;
                if (gr + 8 < n) out[gr + 8] = p1 + b4s;
            }
        }
    }
}

extern "C" void kernel_launch(void* const* d_in, const int* in_sizes, int n_in,
                              void* d_out, int out_size)
{
    const float* x    = (const float*)d_in[0];
    const float* W_ih = (const float*)d_in[1];
    const float* W_hh = (const float*)d_in[2];
    const float* b_ih = (const float*)d_in[3];
    const float* b_hh = (const float*)d_in[4];
    const float* W1   = (const float*)d_in[5];
    const float* b1   = (const float*)d_in[6];
    const float* W2   = (const float*)d_in[7];
    const float* b2   = (const float*)d_in[8];
    const float* W3   = (const float*)d_in[9];
    const float* b3   = (const float*)d_in[10];
    const float* W4   = (const float*)d_in[11];
    const float* b4   = (const float*)d_in[12];
    float* out = (float*)d_out;

    static bool attr_set = false;
    if (!attr_set) {
        cudaFuncSetAttribute(lstm_mlp_mma_kernel,
                             cudaFuncAttributeMaxDynamicSharedMemorySize, SMEM_BYTES);
        attr_set = true;
    }

    lstm_mlp_mma_kernel<<<NBLOCKS, NTHREADS, SMEM_BYTES>>>(
        x, W_ih, W_hh, b_ih, b_hh, W1, b1, W2, b2, W3, b3, W4, b4,
        out, out_size);
}